// round 13
// baseline (speedup 1.0000x reference)
#include <cuda_runtime.h>
#include <cuda_bf16.h>
#include <math.h>

#define ROWS 4096          // B*S = 2*2048
#define DM   1024
#define KW   256           // 1024/4 packed words per row
#define NELEM (ROWS*DM)
#define TSTR 72            // padded smem row stride (words) for flash tiles

typedef unsigned int u32;
typedef unsigned long long ull;

// ------------------------- static device scratch (no allocs) -------------
__device__ u32    g_xq[4][ROWS*KW];     // int8-packed quantized activations
__device__ u32    g_wq[4][DM*KW];       // int8-packed sign weights
__device__ float  g_proj[3][NELEM];     // qp/kp/vp projections (fp32)
__device__ float  g_att[NELEM];         // attention output (concat heads)
__device__ float  g_wpart[4][256][4];   // weight-stat ff partials (s.h,s.l,a.h,a.l)
__device__ float2 g_wmean[4];           // weight mean as ff
__device__ float  g_wbeta[4];
__device__ float4 g_lnp[4][ROWS];       // per-row LN params (muh, mul, rh, rl)
__device__ float  g_rowmax[4][ROWS];    // per-row absmax of normalized vals
__device__ float  g_absmaxf[4];         // global absmax (plain store, no atomics)
__device__ u32    g_maskbits[ROWS*64];  // bit-packed mask, 2048 bits/row

// ------------------------- float-float (ds) arithmetic -------------------
// FP64 on B300 is ~18.4 cyc/warp-instr/SM (crippled). All hot-path "double
// precision" work runs as fp32 pairs on the FMA pipe instead.
struct ff { float h, l; };

__device__ __forceinline__ ff two_sum(float a, float b){
  float s = a + b;
  float bb = s - a;
  float e = (a - (s - bb)) + (b - bb);
  ff r; r.h = s; r.l = e; return r;
}
__device__ __forceinline__ ff ff_norm(float h, float l){
  float s = h + l;
  ff r; r.h = s; r.l = l - (s - h); return r;
}
__device__ __forceinline__ ff ff_addf(ff a, float b){
  ff t = two_sum(a.h, b);
  return ff_norm(t.h, t.l + a.l);
}
__device__ __forceinline__ ff ff_addff(ff a, ff b){
  ff t = two_sum(a.h, b.h);
  return ff_norm(t.h, t.l + (a.l + b.l));
}
__device__ __forceinline__ ff ff_addsq(ff a, float x){  // a += x*x
  float p = x*x;
  float e = fmaf(x, x, -p);
  ff t = two_sum(a.h, p);
  return ff_norm(t.h, t.l + (a.l + e));
}
__device__ __forceinline__ ff ff_mul(ff a, ff b){
  float p = a.h * b.h;
  float e = fmaf(a.h, b.h, -p);
  e = fmaf(a.h, b.l, e);
  e = fmaf(a.l, b.h, e);
  return ff_norm(p, e);
}
// (x - mu) * r in ds, rounded once to fp32. Shared by lnstats and quant so
// rowmax/absmax and quantized values stay mutually consistent.
__device__ __forceinline__ float xnval(float x, float muh, float mul,
                                       float rh, float rl){
  ff d = two_sum(x, -muh);
  float dl = d.l - mul;
  float p = d.h * rh;
  float e = fmaf(d.h, rh, -p);
  e = fmaf(d.h, rl, e);
  e = fmaf(dl,  rh, e);
  return p + e;
}

// ------------------------- f32x2 packed helpers --------------------------
__device__ __forceinline__ ull pk2(float lo, float hi){
  ull r; asm("mov.b64 %0,{%1,%2};" : "=l"(r) : "f"(lo), "f"(hi)); return r;
}
__device__ __forceinline__ float2 upk2(ull v){
  float2 f; asm("mov.b64 {%0,%1},%2;" : "=f"(f.x), "=f"(f.y) : "l"(v)); return f;
}
__device__ __forceinline__ ull f2fma(ull a, ull b, ull c){
  ull r; asm("fma.rn.f32x2 %0,%1,%2,%3;" : "=l"(r) : "l"(a), "l"(b), "l"(c)); return r;
}
__device__ __forceinline__ ull f2mul(ull a, ull b){
  ull r; asm("mul.rn.f32x2 %0,%1,%2;" : "=l"(r) : "l"(a), "l"(b)); return r;
}

__device__ __forceinline__ void cpa16(u32 saddr, const void* g){
  asm volatile("cp.async.cg.shared.global [%0], [%1], 16;" :: "r"(saddr), "l"(g));
}
__device__ __forceinline__ void cpa_commit(){
  asm volatile("cp.async.commit_group;");
}

__device__ __forceinline__ void ldsm4(u32 addr, u32& r0, u32& r1, u32& r2, u32& r3){
  asm volatile("ldmatrix.sync.aligned.m8n8.x4.shared.b16 {%0,%1,%2,%3}, [%4];"
               : "=r"(r0), "=r"(r1), "=r"(r2), "=r"(r3) : "r"(addr));
}

// ------------------------- weight stats (ds) ------------------------------
__global__ void k_wstats1(const float* w0, const float* w1,
                          const float* w2, const float* w3){
  const float* w = (blockIdx.y==0)?w0 : (blockIdx.y==1)?w1 : (blockIdx.y==2)?w2 : w3;
  int base = blockIdx.x * 4096;
  ff s = {0.f,0.f}, a = {0.f,0.f};
  for (int i = threadIdx.x; i < 4096; i += 256){
    float v = w[base + i];
    s = ff_addf(s, v);
    a = ff_addf(a, fabsf(v));
  }
  #pragma unroll
  for (int o=16;o;o>>=1){
    ff t;
    t.h = __shfl_xor_sync(0xffffffffu, s.h, o);
    t.l = __shfl_xor_sync(0xffffffffu, s.l, o);
    s = ff_addff(s, t);
    t.h = __shfl_xor_sync(0xffffffffu, a.h, o);
    t.l = __shfl_xor_sync(0xffffffffu, a.l, o);
    a = ff_addff(a, t);
  }
  __shared__ float sh[8][4];
  if ((threadIdx.x & 31) == 0){
    int wi = threadIdx.x >> 5;
    sh[wi][0] = s.h; sh[wi][1] = s.l; sh[wi][2] = a.h; sh[wi][3] = a.l;
  }
  __syncthreads();
  if (threadIdx.x == 0){
    ff S = {sh[0][0], sh[0][1]}, A = {sh[0][2], sh[0][3]};
    #pragma unroll
    for (int i=1;i<8;i++){
      ff t1 = {sh[i][0], sh[i][1]}; S = ff_addff(S, t1);
      ff t2 = {sh[i][2], sh[i][3]}; A = ff_addff(A, t2);
    }
    g_wpart[blockIdx.y][blockIdx.x][0] = S.h;
    g_wpart[blockIdx.y][blockIdx.x][1] = S.l;
    g_wpart[blockIdx.y][blockIdx.x][2] = A.h;
    g_wpart[blockIdx.y][blockIdx.x][3] = A.l;
  }
}

__global__ void k_wstats2(){
  int wh = blockIdx.x;
  ff s = {g_wpart[wh][threadIdx.x][0], g_wpart[wh][threadIdx.x][1]};
  ff a = {g_wpart[wh][threadIdx.x][2], g_wpart[wh][threadIdx.x][3]};
  #pragma unroll
  for (int o=16;o;o>>=1){
    ff t;
    t.h = __shfl_xor_sync(0xffffffffu, s.h, o);
    t.l = __shfl_xor_sync(0xffffffffu, s.l, o);
    s = ff_addff(s, t);
    t.h = __shfl_xor_sync(0xffffffffu, a.h, o);
    t.l = __shfl_xor_sync(0xffffffffu, a.l, o);
    a = ff_addff(a, t);
  }
  __shared__ float sh[8][4];
  if ((threadIdx.x & 31) == 0){
    int wi = threadIdx.x >> 5;
    sh[wi][0] = s.h; sh[wi][1] = s.l; sh[wi][2] = a.h; sh[wi][3] = a.l;
  }
  __syncthreads();
  if (threadIdx.x == 0){
    ff S = {sh[0][0], sh[0][1]}, A = {sh[0][2], sh[0][3]};
    #pragma unroll
    for (int i=1;i<8;i++){
      ff t1 = {sh[i][0], sh[i][1]}; S = ff_addff(S, t1);
      ff t2 = {sh[i][2], sh[i][3]}; A = ff_addff(A, t2);
    }
    // exact scale by 2^-20
    float2 mean; mean.x = S.h * (1.0f/1048576.0f); mean.y = S.l * (1.0f/1048576.0f);
    g_wmean[wh] = mean;
    g_wbeta[wh] = A.h * (1.0f/1048576.0f) + A.l * (1.0f/1048576.0f);
  }
}

__global__ void k_wquant(const float* w0, const float* w1,
                         const float* w2, const float* w3){
  int wh = blockIdx.y;
  const float* w = (wh==0)?w0 : (wh==1)?w1 : (wh==2)?w2 : w3;
  float2 mu = g_wmean[wh];
  int o = blockIdx.x;
  float4 v = ((const float4*)(w + (size_t)o*DM))[threadIdx.x];
  int r[4];
  float xs[4] = {v.x, v.y, v.z, v.w};
  #pragma unroll
  for (int i=0;i<4;i++){
    ff d = two_sum(xs[i], -mu.x);
    float t = d.h + (d.l - mu.y);       // sign of (x - mean), ds accuracy
    r[i] = (t > 0.f) ? 1 : ((t < 0.f) ? -1 : 0);
  }
  g_wq[wh][(size_t)o*KW + threadIdx.x] =
      (u32)(r[0] & 0xff) | ((u32)(r[1] & 0xff) << 8) |
      ((u32)(r[2] & 0xff) << 16) | ((u32)(r[3] & 0xff) << 24);
}

// ---- LN stats: warp per row, ds arithmetic, ZERO FP64 -------------------
__device__ __forceinline__ void lnstats_warp(const float* src, int slot, int row){
  int lane = threadIdx.x & 31;
  const float4* p = (const float4*)(src + (size_t)row*DM);
  float4 vv[8];
  ff s = {0.f,0.f}, sq = {0.f,0.f};
  #pragma unroll
  for (int i=0;i<8;i++){
    float4 v = p[i*32 + lane];
    vv[i] = v;
    s = ff_addf(s, v.x);  s = ff_addf(s, v.y);
    s = ff_addf(s, v.z);  s = ff_addf(s, v.w);
    sq = ff_addsq(sq, v.x); sq = ff_addsq(sq, v.y);
    sq = ff_addsq(sq, v.z); sq = ff_addsq(sq, v.w);
  }
  #pragma unroll
  for (int o=16;o;o>>=1){
    ff t;
    t.h = __shfl_xor_sync(0xffffffffu, s.h, o);
    t.l = __shfl_xor_sync(0xffffffffu, s.l, o);
    s = ff_addff(s, t);
    t.h = __shfl_xor_sync(0xffffffffu, sq.h, o);
    t.l = __shfl_xor_sync(0xffffffffu, sq.l, o);
    sq = ff_addff(sq, t);
  }
  // mu = s/1024, var = sq/1024 - mu^2 + 1e-5 (ds)
  ff mu;  mu.h = s.h  * (1.0f/1024.0f); mu.l = s.l  * (1.0f/1024.0f);
  ff qm;  qm.h = sq.h * (1.0f/1024.0f); qm.l = sq.l * (1.0f/1024.0f);
  ff m2 = ff_mul(mu, mu);
  ff nm2; nm2.h = -m2.h; nm2.l = -m2.l;
  ff var = ff_addff(qm, nm2);
  var = ff_addf(var, 1e-5f);
  // r = 1/sqrt(var): fp32 seed + fp32 Newton + 2 ds Newton iterations
  float y0 = rsqrtf(var.h);
  y0 = y0 * (1.5f - 0.5f * var.h * y0 * y0);
  ff y = {y0, 0.f};
  #pragma unroll
  for (int it=0; it<2; it++){
    ff t = ff_mul(y, y);
    t = ff_mul(var, t);
    ff u; u.h = -0.5f*t.h; u.l = -0.5f*t.l;   // exact scale
    u = ff_addf(u, 1.5f);
    y = ff_mul(y, u);
  }
  float am = 0.f;
  #pragma unroll
  for (int i=0;i<8;i++){
    float a0 = xnval(vv[i].x, mu.h, mu.l, y.h, y.l);
    float a1 = xnval(vv[i].y, mu.h, mu.l, y.h, y.l);
    float a2 = xnval(vv[i].z, mu.h, mu.l, y.h, y.l);
    float a3 = xnval(vv[i].w, mu.h, mu.l, y.h, y.l);
    am = fmaxf(am, fmaxf(fmaxf(fabsf(a0), fabsf(a1)), fmaxf(fabsf(a2), fabsf(a3))));
  }
  #pragma unroll
  for (int o=16;o;o>>=1) am = fmaxf(am, __shfl_xor_sync(0xffffffffu, am, o));
  if (lane == 0){
    g_lnp[slot][row] = make_float4(mu.h, mu.l, y.h, y.l);
    g_rowmax[slot][row] = am;
  }
}

__global__ void __launch_bounds__(256) k_lnstats3(const float* q, const float* k, const float* v){
  int slot = blockIdx.y;
  const float* src = (slot==0)?q : (slot==1)?k : v;
  lnstats_warp(src, slot, blockIdx.x*8 + (threadIdx.x >> 5));
}
__global__ void __launch_bounds__(256) k_lnstats1(){
  lnstats_warp(g_att, 3, blockIdx.x*8 + (threadIdx.x >> 5));
}

// global absmax: deterministic tree over 4096 rowmax values, one block/slot
__global__ void k_absmax(int slot0){
  int slot = slot0 + blockIdx.x;
  __shared__ float shm[8];
  float m = 0.f;
  for (int i = threadIdx.x; i < ROWS; i += 256)
    m = fmaxf(m, g_rowmax[slot][i]);
  #pragma unroll
  for (int o=16;o;o>>=1) m = fmaxf(m, __shfl_xor_sync(0xffffffffu, m, o));
  if ((threadIdx.x & 31) == 0) shm[threadIdx.x>>5] = m;
  __syncthreads();
  if (threadIdx.x == 0){
    float M = shm[0];
    #pragma unroll
    for (int i=1;i<8;i++) M = fmaxf(M, shm[i]);
    g_absmaxf[slot] = M;
  }
}

__device__ __forceinline__ int qv(float x, float qs){
  int v = (int)rintf(x * qs);        // RN = round half to even, matches jnp.round
  return (v == 128) ? -128 : v;      // int8 wrap of the +128 element
}

// quantize: warp per row, ds xnval identical to lnstats, ZERO FP64.
__device__ __forceinline__ void quant_warp(const float* src, int slot, int row){
  int lane = threadIdx.x & 31;
  float qs = 128.0f / g_absmaxf[slot];
  float4 lp = g_lnp[slot][row];        // (muh, mul, rh, rl)
  const float4* p = (const float4*)(src + (size_t)row*DM);
  u32* dst = g_xq[slot] + (size_t)row*KW;
  #pragma unroll
  for (int i=0;i<8;i++){
    float4 v = p[i*32 + lane];
    float a0 = xnval(v.x, lp.x, lp.y, lp.z, lp.w);
    float a1 = xnval(v.y, lp.x, lp.y, lp.z, lp.w);
    float a2 = xnval(v.z, lp.x, lp.y, lp.z, lp.w);
    float a3 = xnval(v.w, lp.x, lp.y, lp.z, lp.w);
    int a = qv(a0,qs), b = qv(a1,qs), c = qv(a2,qs), d = qv(a3,qs);
    dst[i*32 + lane] =
        (u32)(a & 0xff) | ((u32)(b & 0xff) << 8) |
        ((u32)(c & 0xff) << 16) | ((u32)(d & 0xff) << 24);
  }
}
__global__ void __launch_bounds__(256) k_quant3(const float* q, const float* k, const float* v){
  int slot = blockIdx.y;
  const float* src = (slot==0)?q : (slot==1)?k : v;
  quant_warp(src, slot, blockIdx.x*8 + (threadIdx.x >> 5));
}
__global__ void __launch_bounds__(256) k_quant1(){
  quant_warp(g_att, 3, blockIdx.x*8 + (threadIdx.x >> 5));
}

// ---------------- IMMA GEMM v2: ldmatrix fragments, K=128B stages --------
__global__ void __launch_bounds__(256) k_gemm(float* Cext, int slot0){
  int slot = slot0 + blockIdx.z;
  const u32* X = g_xq[slot];
  const u32* W = g_wq[slot];
  float* C = (slot < 3) ? g_proj[slot] : Cext;
  int m0 = blockIdx.y * 128, n0 = blockIdx.x * 128;

  __shared__ u32 As[128*36];
  __shared__ u32 Bs[128*36];

  int tid = threadIdx.x;
  int lane = tid & 31, warp = tid >> 5;
  int wm = (warp >> 1) * 32, wn = (warp & 1) * 64;

  u32 as_base = (u32)__cvta_generic_to_shared(As);
  u32 bs_base = (u32)__cvta_generic_to_shared(Bs);

  u32 a_word = (u32)((wm + ((lane>>3)&1)*8 + (lane&7))*36 + (lane>>4)*4);
  u32 b_word = (u32)((wn + ((lane>>4)&1)*8 + (lane&7))*36 + ((lane>>3)&1)*4);

  int acc[2][8][4];
  #pragma unroll
  for (int mt=0;mt<2;mt++)
    #pragma unroll
    for (int nt=0;nt<8;nt++)
      #pragma unroll
      for (int i=0;i<4;i++) acc[mt][nt][i] = 0;

  for (int st = 0; st < 8; st++){            // 8 stages of K=128 bytes
    #pragma unroll
    for (int l=0;l<4;l++){
      int idx = tid + l*256;                 // 0..1023
      int row = idx >> 3, seg = (idx & 7) * 4;
      *(uint4*)&As[row*36 + seg] = *(const uint4*)(X + (size_t)(m0+row)*KW + st*32 + seg);
      *(uint4*)&Bs[row*36 + seg] = *(const uint4*)(W + (size_t)(n0+row)*KW + st*32 + seg);
    }
    __syncthreads();
    #pragma unroll
    for (int s=0;s<4;s++){                   // four k32 steps per stage
      u32 afr[2][4], bfr[8][2];
      #pragma unroll
      for (int mt=0;mt<2;mt++){
        u32 addr = as_base + (a_word + (u32)(mt*16*36 + s*8))*4u;
        ldsm4(addr, afr[mt][0], afr[mt][1], afr[mt][2], afr[mt][3]);
      }
      #pragma unroll
      for (int np=0;np<4;np++){
        u32 addr = bs_base + (b_word + (u32)(np*16*36 + s*8))*4u;
        ldsm4(addr, bfr[2*np][0], bfr[2*np][1], bfr[2*np+1][0], bfr[2*np+1][1]);
      }
      #pragma unroll
      for (int mt=0;mt<2;mt++)
        #pragma unroll
        for (int nt=0;nt<8;nt++){
          asm volatile(
            "mma.sync.aligned.m16n8k32.row.col.s32.s8.s8.s32 "
            "{%0,%1,%2,%3}, {%4,%5,%6,%7}, {%8,%9}, {%0,%1,%2,%3};"
            : "+r"(acc[mt][nt][0]), "+r"(acc[mt][nt][1]),
              "+r"(acc[mt][nt][2]), "+r"(acc[mt][nt][3])
            : "r"(afr[mt][0]), "r"(afr[mt][1]), "r"(afr[mt][2]), "r"(afr[mt][3]),
              "r"(bfr[nt][0]), "r"(bfr[nt][1]));
        }
    }
    __syncthreads();
  }

  float scale = (g_absmaxf[slot] / 128.0f) * g_wbeta[slot];   // dequant * beta
  #pragma unroll
  for (int mt=0;mt<2;mt++){
    #pragma unroll
    for (int nt=0;nt<8;nt++){
      int r0 = m0 + wm + mt*16 + (lane >> 2);
      int c0 = n0 + wn + nt*8 + 2*(lane & 3);
      float2 v0, v1;
      v0.x = (float)acc[mt][nt][0] * scale;
      v0.y = (float)acc[mt][nt][1] * scale;
      v1.x = (float)acc[mt][nt][2] * scale;
      v1.y = (float)acc[mt][nt][3] * scale;
      *(float2*)(C + (size_t)r0*DM + c0)     = v0;
      *(float2*)(C + (size_t)(r0+8)*DM + c0) = v1;
    }
  }
}

__global__ void k_maskpack(const int* mask){
  int row = blockIdx.x;                 // b*2048 + q
  int lane = threadIdx.x & 31, wd = threadIdx.x >> 5;
  for (int w8 = 0; w8 < 8; w8++){
    int kk = w8*256 + threadIdx.x;
    int mv = mask[(size_t)row*2048 + kk];
    u32 bits = __ballot_sync(0xffffffffu, mv != 0);
    if (lane == 0) g_maskbits[(size_t)row*64 + w8*8 + wd] = bits;
  }
}

// Flash attention fp32/FFMA2. dk-split (2 threads/query) x 2 queries/thread
// (R9-proven, UNCHANGED). Smem rows: halves at word off 0/36, stride 72.
__global__ void __launch_bounds__(128,2) k_flash(){
  extern __shared__ float fsm[];        // K: [2][64][72]  V: [2][64][72]
  float* KS = fsm;
  float* VS = fsm + 2*64*TSTR;

  int tid = threadIdx.x;
  int p  = tid >> 1;                    // query pair index 0..63
  int hf = tid & 1;                     // dim half
  int qt = blockIdx.x & 15;
  int h  = (blockIdx.x >> 4) & 15;
  int b  = blockIdx.x >> 8;
  int qa = qt*128 + p;                  // query A; query B = qa + 64
  size_t qoffA = ((size_t)(b*2048 + qa))*DM + h*64 + hf*32;
  size_t qoffB = qoffA + (size_t)64*DM;
  const float* QP = g_proj[0];
  const float* KP = g_proj[1];
  const float* VP = g_proj[2];

  u32 ks_base = (u32)__cvta_generic_to_shared(KS);
  u32 vs_base = (u32)__cvta_generic_to_shared(VS);

  ull q2a[16], q2b[16];
  {
    const float4* pa = (const float4*)(QP + qoffA);
    const float4* pb = (const float4*)(QP + qoffB);
    #pragma unroll
    for (int t=0;t<8;t++){
      float4 fa = pa[t], fb = pb[t];
      q2a[2*t]   = pk2(fa.x*0.125f, fa.y*0.125f);  // fold 1/sqrt(64)
      q2a[2*t+1] = pk2(fa.z*0.125f, fa.w*0.125f);
      q2b[2*t]   = pk2(fb.x*0.125f, fb.y*0.125f);
      q2b[2*t+1] = pk2(fb.z*0.125f, fb.w*0.125f);
    }
  }
  ull acc2a[16], acc2b[16];
  #pragma unroll
  for (int t=0;t<16;t++){ acc2a[t] = 0ull; acc2b[t] = 0ull; }
  float ma = -1e30f, sa = 0.f, mb = -1e30f, sb = 0.f;

  const u32* mbaseA = g_maskbits + (size_t)(b*2048 + qa)*64;
  const u32* mbaseB = mbaseA + 64*64;

  #pragma unroll
  for (int l=0;l<8;l++){
    int i = tid + l*128;               // 0..1023
    int row = i >> 4, c = i & 15;
    int woff = row*TSTR + ((c < 8) ? c*4 : 36 + (c-8)*4);
    size_t goff = ((size_t)(b*2048 + row))*DM + h*64 + c*4;
    cpa16(ks_base + (u32)(woff*4), KP + goff);
    cpa16(vs_base + (u32)(woff*4), VP + goff);
  }
  cpa_commit();

  for (int kt = 0; kt < 32; kt++){
    int buf = kt & 1;
    if (kt < 31){
      int nb = buf ^ 1;
      #pragma unroll
      for (int l=0;l<8;l++){
        int i = tid + l*128;
        int row = i >> 4, c = i & 15;
        int woff = (nb*64 + row)*TSTR + ((c < 8) ? c*4 : 36 + (c-8)*4);
        size_t goff = ((size_t)(b*2048 + (kt+1)*64 + row))*DM + h*64 + c*4;
        cpa16(ks_base + (u32)(woff*4), KP + goff);
        cpa16(vs_base + (u32)(woff*4), VP + goff);
      }
      cpa_commit();
      asm volatile("cp.async.wait_group 1;");
    } else {
      asm volatile("cp.async.wait_group 0;");
    }
    __syncthreads();

    const float* kbuf = KS + buf*64*TSTR + hf*36;
    const float* vbuf = VS + buf*64*TSTR + hf*36;
    int k0 = kt*64;

    #pragma unroll 1
    for (int j0 = 0; j0 < 64; j0 += 8){
      u32 mbA = mbaseA[(k0 + j0) >> 5] >> (j0 & 31);
      u32 mbB = mbaseB[(k0 + j0) >> 5] >> (j0 & 31);
      float lgA[8], lgB[8];
      #pragma unroll
      for (int jj=0;jj<8;jj++){
        const ulonglong2* kp2 = (const ulonglong2*)(kbuf + (j0+jj)*TSTR);
        ull d0a = 0ull, d1a = 0ull, d0b = 0ull, d1b = 0ull;
        #pragma unroll
        for (int t=0;t<4;t++){
          ulonglong2 k1 = kp2[2*t];        // LDS.128, conflict-free pair
          ulonglong2 k2 = kp2[2*t+1];
          d0a = f2fma(q2a[4*t],   k1.x, d0a);
          d1a = f2fma(q2a[4*t+1], k1.y, d1a);
          d0a = f2fma(q2a[4*t+2], k2.x, d0a);
          d1a = f2fma(q2a[4*t+3], k2.y, d1a);
          d0b = f2fma(q2b[4*t],   k1.x, d0b);
          d1b = f2fma(q2b[4*t+1], k1.y, d1b);
          d0b = f2fma(q2b[4*t+2], k2.x, d0b);
          d1b = f2fma(q2b[4*t+3], k2.y, d1b);
        }
        float2 a0 = upk2(d0a), a1 = upk2(d1a);
        float2 b0 = upk2(d0b), b1 = upk2(d1b);
        float hA = (a0.x + a0.y) + (a1.x + a1.y);
        float hB = (b0.x + b0.y) + (b1.x + b1.y);
        float lvA = hA + __shfl_xor_sync(0xffffffffu, hA, 1);
        float lvB = hB + __shfl_xor_sync(0xffffffffu, hB, 1);
        lgA[jj] = ((mbA >> jj) & 1u) ? lvA : -1e9f;
        lgB[jj] = ((mbB >> jj) & 1u) ? lvB : -1e9f;
      }
      float cmA = lgA[0], cmB = lgB[0];
      #pragma unroll
      for (int jj=1;jj<8;jj++){
        cmA = fmaxf(cmA, lgA[jj]);
        cmB = fmaxf(cmB, lgB[jj]);
      }
      if (cmA > ma){
        float r = __expf(ma - cmA);
        sa *= r;
        ull rr = pk2(r, r);
        #pragma unroll
        for (int t=0;t<16;t++) acc2a[t] = f2mul(acc2a[t], rr);
        ma = cmA;
      }
      if (cmB > mb){
        float r = __expf(mb - cmB);
        sb *= r;
        ull rr = pk2(r, r);
        #pragma unroll
        for (int t=0;t<16;t++) acc2b[t] = f2mul(acc2b[t], rr);
        mb = cmB;
      }
      float pA[8], pB[8]; float psA = 0.f, psB = 0.f;
      #pragma unroll
      for (int jj=0;jj<8;jj++){
        pA[jj] = __expf(lgA[jj] - ma); psA += pA[jj];
        pB[jj] = __expf(lgB[jj] - mb); psB += pB[jj];
      }
      sa += psA; sb += psB;
      #pragma unroll
      for (int jj=0;jj<8;jj++){
        ull ppa = pk2(pA[jj], pA[jj]);
        ull ppb = pk2(pB[jj], pB[jj]);
        const ulonglong2* vp2 = (const ulonglong2*)(vbuf + (j0+jj)*TSTR);
        #pragma unroll
        for (int t=0;t<4;t++){
          ulonglong2 v1 = vp2[2*t];
          ulonglong2 v2 = vp2[2*t+1];
          acc2a[4*t]   = f2fma(ppa, v1.x, acc2a[4*t]);
          acc2a[4*t+1] = f2fma(ppa, v1.y, acc2a[4*t+1]);
          acc2a[4*t+2] = f2fma(ppa, v2.x, acc2a[4*t+2]);
          acc2a[4*t+3] = f2fma(ppa, v2.y, acc2a[4*t+3]);
          acc2b[4*t]   = f2fma(ppb, v1.x, acc2b[4*t]);
          acc2b[4*t+1] = f2fma(ppb, v1.y, acc2b[4*t+1]);
          acc2b[4*t+2] = f2fma(ppb, v2.x, acc2b[4*t+2]);
          acc2b[4*t+3] = f2fma(ppb, v2.y, acc2b[4*t+3]);
        }
      }
    }
    __syncthreads();
  }
  float invA = 1.0f / sa, invB = 1.0f / sb;
  float* orA = g_att + qoffA;
  float* orB = g_att + qoffB;
  #pragma unroll
  for (int t=0;t<16;t++){
    float2 fa = upk2(acc2a[t]);
    fa.x *= invA; fa.y *= invA;
    *(float2*)(orA + 2*t) = fa;
    float2 fb = upk2(acc2b[t]);
    fb.x *= invB; fb.y *= invB;
    *(float2*)(orB + 2*t) = fb;
  }
}

// ------------------------- launcher --------------------------------------
extern "C" void kernel_launch(void* const* d_in, const int* in_sizes, int n_in,
                              void* d_out, int out_size){
  const float* q   = (const float*)d_in[0];
  const float* k   = (const float*)d_in[1];
  const float* v   = (const float*)d_in[2];
  const int*  mask = (const int*)  d_in[3];
  const float* w0  = (const float*)d_in[4];  // wq_w
  const float* w1  = (const float*)d_in[5];  // wk_w
  const float* w2  = (const float*)d_in[6];  // wv_w
  const float* w3  = (const float*)d_in[7];  // w0_w
  float* out = (float*)d_out;

  const int FLASH_SMEM = 4*64*TSTR*4;   // 73728 bytes

  static int smem_set = 0;
  if (!smem_set){
    cudaFuncSetAttribute(k_flash, cudaFuncAttributeMaxDynamicSharedMemorySize, FLASH_SMEM);
    smem_set = 1;
  }

  k_wstats1<<<dim3(256,4),256>>>(w0,w1,w2,w3);   // (0)
  k_wstats2<<<4,256>>>();                        // (1)
  k_wquant<<<dim3(1024,4),256>>>(w0,w1,w2,w3);   // (2)

  k_lnstats3<<<dim3(512,3),256>>>(q,k,v);        // (3) <- profiled: FP64-theory test
  k_absmax<<<3,256>>>(0);                        // (4)
  k_quant3<<<dim3(512,3),256>>>(q,k,v);          // (5)

  k_gemm<<<dim3(8,32,3),256>>>(nullptr,0);       // (6) qp,kp,vp

  k_maskpack<<<4096,256>>>(mask);                // (7)
  k_flash<<<512,128,FLASH_SMEM>>>();             // (8)

  k_lnstats1<<<512,256>>>();                     // (9)
  k_absmax<<<1,256>>>(3);                        // (10)
  k_quant1<<<512,256>>>();                       // (11)
  k_gemm<<<dim3(8,32,1),256>>>(out,3);           // (12)
}

// round 14
// speedup vs baseline: 1.6264x; 1.6264x over previous
#include <cuda_runtime.h>
#include <cuda_bf16.h>
#include <math.h>

#define ROWS 4096          // B*S = 2*2048
#define DM   1024
#define KW   256           // 1024/4 packed words per row
#define NELEM (ROWS*DM)
#define TSTR 72            // padded smem row stride (words) for flash tiles

typedef unsigned int u32;
typedef unsigned long long ull;

// ------------------------- static device scratch (no allocs) -------------
__device__ u32    g_xq[4][ROWS*KW];     // int8-packed quantized activations
__device__ u32    g_wq[4][DM*KW];       // int8-packed sign weights
__device__ float  g_proj[3][NELEM];     // qp/kp/vp projections (fp32)
__device__ float  g_att[NELEM];         // attention output (concat heads)
__device__ float  g_wpart[4][256][4];   // weight-stat ff partials (s.h,s.l,a.h,a.l)
__device__ float2 g_wmean[4];           // weight mean as ff
__device__ float  g_wbeta[4];
__device__ float4 g_lnp[4][ROWS];       // per-row LN params (muh, mul, rh, rl)
__device__ float  g_rowmax[4][ROWS];    // per-row absmax of normalized vals
__device__ float  g_absmaxf[4];         // global absmax (plain store, no atomics)
__device__ u32    g_maskbits[ROWS*64];  // bit-packed mask, 2048 bits/row

// ------------------------- float-float (ds) arithmetic -------------------
// FP64 on B300 is ~18.4 cyc/warp-instr/SM (crippled). All hot-path "double
// precision" work runs as fp32 pairs on the FMA pipe instead. (R13: verified
// bit-identical rel_err vs the FP64 version, 6x faster.)
struct ff { float h, l; };

__device__ __forceinline__ ff two_sum(float a, float b){
  float s = a + b;
  float bb = s - a;
  float e = (a - (s - bb)) + (b - bb);
  ff r; r.h = s; r.l = e; return r;
}
__device__ __forceinline__ ff ff_norm(float h, float l){
  float s = h + l;
  ff r; r.h = s; r.l = l - (s - h); return r;
}
__device__ __forceinline__ ff ff_addf(ff a, float b){
  ff t = two_sum(a.h, b);
  return ff_norm(t.h, t.l + a.l);
}
__device__ __forceinline__ ff ff_addff(ff a, ff b){
  ff t = two_sum(a.h, b.h);
  return ff_norm(t.h, t.l + (a.l + b.l));
}
__device__ __forceinline__ ff ff_addsq(ff a, float x){  // a += x*x
  float p = x*x;
  float e = fmaf(x, x, -p);
  ff t = two_sum(a.h, p);
  return ff_norm(t.h, t.l + (a.l + e));
}
__device__ __forceinline__ ff ff_mul(ff a, ff b){
  float p = a.h * b.h;
  float e = fmaf(a.h, b.h, -p);
  e = fmaf(a.h, b.l, e);
  e = fmaf(a.l, b.h, e);
  return ff_norm(p, e);
}
// (x - mu) * r in ds, rounded once to fp32. Shared by lnstats and quant so
// rowmax/absmax and quantized values stay mutually consistent.
__device__ __forceinline__ float xnval(float x, float muh, float mul,
                                       float rh, float rl){
  ff d = two_sum(x, -muh);
  float dl = d.l - mul;
  float p = d.h * rh;
  float e = fmaf(d.h, rh, -p);
  e = fmaf(d.h, rl, e);
  e = fmaf(dl,  rh, e);
  return p + e;
}

// ------------------------- f32x2 packed helpers --------------------------
__device__ __forceinline__ ull pk2(float lo, float hi){
  ull r; asm("mov.b64 %0,{%1,%2};" : "=l"(r) : "f"(lo), "f"(hi)); return r;
}
__device__ __forceinline__ float2 upk2(ull v){
  float2 f; asm("mov.b64 {%0,%1},%2;" : "=f"(f.x), "=f"(f.y) : "l"(v)); return f;
}
__device__ __forceinline__ ull f2fma(ull a, ull b, ull c){
  ull r; asm("fma.rn.f32x2 %0,%1,%2,%3;" : "=l"(r) : "l"(a), "l"(b), "l"(c)); return r;
}
__device__ __forceinline__ ull f2mul(ull a, ull b){
  ull r; asm("mul.rn.f32x2 %0,%1,%2;" : "=l"(r) : "l"(a), "l"(b)); return r;
}

__device__ __forceinline__ void cpa16(u32 saddr, const void* g){
  asm volatile("cp.async.cg.shared.global [%0], [%1], 16;" :: "r"(saddr), "l"(g));
}
__device__ __forceinline__ void cpa_commit(){
  asm volatile("cp.async.commit_group;");
}

__device__ __forceinline__ void ldsm4(u32 addr, u32& r0, u32& r1, u32& r2, u32& r3){
  asm volatile("ldmatrix.sync.aligned.m8n8.x4.shared.b16 {%0,%1,%2,%3}, [%4];"
               : "=r"(r0), "=r"(r1), "=r"(r2), "=r"(r3) : "r"(addr));
}

// ------------------------- weight stats (ds) ------------------------------
__global__ void k_wstats1(const float* w0, const float* w1,
                          const float* w2, const float* w3){
  const float* w = (blockIdx.y==0)?w0 : (blockIdx.y==1)?w1 : (blockIdx.y==2)?w2 : w3;
  int base = blockIdx.x * 4096;
  ff s = {0.f,0.f}, a = {0.f,0.f};
  for (int i = threadIdx.x; i < 4096; i += 256){
    float v = w[base + i];
    s = ff_addf(s, v);
    a = ff_addf(a, fabsf(v));
  }
  #pragma unroll
  for (int o=16;o;o>>=1){
    ff t;
    t.h = __shfl_xor_sync(0xffffffffu, s.h, o);
    t.l = __shfl_xor_sync(0xffffffffu, s.l, o);
    s = ff_addff(s, t);
    t.h = __shfl_xor_sync(0xffffffffu, a.h, o);
    t.l = __shfl_xor_sync(0xffffffffu, a.l, o);
    a = ff_addff(a, t);
  }
  __shared__ float sh[8][4];
  if ((threadIdx.x & 31) == 0){
    int wi = threadIdx.x >> 5;
    sh[wi][0] = s.h; sh[wi][1] = s.l; sh[wi][2] = a.h; sh[wi][3] = a.l;
  }
  __syncthreads();
  if (threadIdx.x == 0){
    ff S = {sh[0][0], sh[0][1]}, A = {sh[0][2], sh[0][3]};
    #pragma unroll
    for (int i=1;i<8;i++){
      ff t1 = {sh[i][0], sh[i][1]}; S = ff_addff(S, t1);
      ff t2 = {sh[i][2], sh[i][3]}; A = ff_addff(A, t2);
    }
    g_wpart[blockIdx.y][blockIdx.x][0] = S.h;
    g_wpart[blockIdx.y][blockIdx.x][1] = S.l;
    g_wpart[blockIdx.y][blockIdx.x][2] = A.h;
    g_wpart[blockIdx.y][blockIdx.x][3] = A.l;
  }
}

__global__ void k_wstats2(){
  int wh = blockIdx.x;
  ff s = {g_wpart[wh][threadIdx.x][0], g_wpart[wh][threadIdx.x][1]};
  ff a = {g_wpart[wh][threadIdx.x][2], g_wpart[wh][threadIdx.x][3]};
  #pragma unroll
  for (int o=16;o;o>>=1){
    ff t;
    t.h = __shfl_xor_sync(0xffffffffu, s.h, o);
    t.l = __shfl_xor_sync(0xffffffffu, s.l, o);
    s = ff_addff(s, t);
    t.h = __shfl_xor_sync(0xffffffffu, a.h, o);
    t.l = __shfl_xor_sync(0xffffffffu, a.l, o);
    a = ff_addff(a, t);
  }
  __shared__ float sh[8][4];
  if ((threadIdx.x & 31) == 0){
    int wi = threadIdx.x >> 5;
    sh[wi][0] = s.h; sh[wi][1] = s.l; sh[wi][2] = a.h; sh[wi][3] = a.l;
  }
  __syncthreads();
  if (threadIdx.x == 0){
    ff S = {sh[0][0], sh[0][1]}, A = {sh[0][2], sh[0][3]};
    #pragma unroll
    for (int i=1;i<8;i++){
      ff t1 = {sh[i][0], sh[i][1]}; S = ff_addff(S, t1);
      ff t2 = {sh[i][2], sh[i][3]}; A = ff_addff(A, t2);
    }
    float2 mean; mean.x = S.h * (1.0f/1048576.0f); mean.y = S.l * (1.0f/1048576.0f);
    g_wmean[wh] = mean;
    g_wbeta[wh] = A.h * (1.0f/1048576.0f) + A.l * (1.0f/1048576.0f);
  }
}

__global__ void k_wquant(const float* w0, const float* w1,
                         const float* w2, const float* w3){
  int wh = blockIdx.y;
  const float* w = (wh==0)?w0 : (wh==1)?w1 : (wh==2)?w2 : w3;
  float2 mu = g_wmean[wh];
  int o = blockIdx.x;
  float4 v = ((const float4*)(w + (size_t)o*DM))[threadIdx.x];
  int r[4];
  float xs[4] = {v.x, v.y, v.z, v.w};
  #pragma unroll
  for (int i=0;i<4;i++){
    ff d = two_sum(xs[i], -mu.x);
    float t = d.h + (d.l - mu.y);       // sign of (x - mean), ds accuracy
    r[i] = (t > 0.f) ? 1 : ((t < 0.f) ? -1 : 0);
  }
  g_wq[wh][(size_t)o*KW + threadIdx.x] =
      (u32)(r[0] & 0xff) | ((u32)(r[1] & 0xff) << 8) |
      ((u32)(r[2] & 0xff) << 16) | ((u32)(r[3] & 0xff) << 24);
}

// ---- LN stats: warp per row, ds arithmetic, ZERO FP64 -------------------
__device__ __forceinline__ void lnstats_warp(const float* src, int slot, int row){
  int lane = threadIdx.x & 31;
  const float4* p = (const float4*)(src + (size_t)row*DM);
  float4 vv[8];
  ff s = {0.f,0.f}, sq = {0.f,0.f};
  #pragma unroll
  for (int i=0;i<8;i++){
    float4 v = p[i*32 + lane];
    vv[i] = v;
    s = ff_addf(s, v.x);  s = ff_addf(s, v.y);
    s = ff_addf(s, v.z);  s = ff_addf(s, v.w);
    sq = ff_addsq(sq, v.x); sq = ff_addsq(sq, v.y);
    sq = ff_addsq(sq, v.z); sq = ff_addsq(sq, v.w);
  }
  #pragma unroll
  for (int o=16;o;o>>=1){
    ff t;
    t.h = __shfl_xor_sync(0xffffffffu, s.h, o);
    t.l = __shfl_xor_sync(0xffffffffu, s.l, o);
    s = ff_addff(s, t);
    t.h = __shfl_xor_sync(0xffffffffu, sq.h, o);
    t.l = __shfl_xor_sync(0xffffffffu, sq.l, o);
    sq = ff_addff(sq, t);
  }
  ff mu;  mu.h = s.h  * (1.0f/1024.0f); mu.l = s.l  * (1.0f/1024.0f);
  ff qm;  qm.h = sq.h * (1.0f/1024.0f); qm.l = sq.l * (1.0f/1024.0f);
  ff m2 = ff_mul(mu, mu);
  ff nm2; nm2.h = -m2.h; nm2.l = -m2.l;
  ff var = ff_addff(qm, nm2);
  var = ff_addf(var, 1e-5f);
  float y0 = rsqrtf(var.h);
  y0 = y0 * (1.5f - 0.5f * var.h * y0 * y0);
  ff y = {y0, 0.f};
  #pragma unroll
  for (int it=0; it<2; it++){
    ff t = ff_mul(y, y);
    t = ff_mul(var, t);
    ff u; u.h = -0.5f*t.h; u.l = -0.5f*t.l;
    u = ff_addf(u, 1.5f);
    y = ff_mul(y, u);
  }
  float am = 0.f;
  #pragma unroll
  for (int i=0;i<8;i++){
    float a0 = xnval(vv[i].x, mu.h, mu.l, y.h, y.l);
    float a1 = xnval(vv[i].y, mu.h, mu.l, y.h, y.l);
    float a2 = xnval(vv[i].z, mu.h, mu.l, y.h, y.l);
    float a3 = xnval(vv[i].w, mu.h, mu.l, y.h, y.l);
    am = fmaxf(am, fmaxf(fmaxf(fabsf(a0), fabsf(a1)), fmaxf(fabsf(a2), fabsf(a3))));
  }
  #pragma unroll
  for (int o=16;o;o>>=1) am = fmaxf(am, __shfl_xor_sync(0xffffffffu, am, o));
  if (lane == 0){
    g_lnp[slot][row] = make_float4(mu.h, mu.l, y.h, y.l);
    g_rowmax[slot][row] = am;
  }
}

__global__ void __launch_bounds__(256) k_lnstats3(const float* q, const float* k, const float* v){
  int slot = blockIdx.y;
  const float* src = (slot==0)?q : (slot==1)?k : v;
  lnstats_warp(src, slot, blockIdx.x*8 + (threadIdx.x >> 5));
}
__global__ void __launch_bounds__(256) k_lnstats1(){
  lnstats_warp(g_att, 3, blockIdx.x*8 + (threadIdx.x >> 5));
}

// global absmax: deterministic tree over 4096 rowmax values, one block/slot
__global__ void k_absmax(int slot0){
  int slot = slot0 + blockIdx.x;
  __shared__ float shm[8];
  float m = 0.f;
  for (int i = threadIdx.x; i < ROWS; i += 256)
    m = fmaxf(m, g_rowmax[slot][i]);
  #pragma unroll
  for (int o=16;o;o>>=1) m = fmaxf(m, __shfl_xor_sync(0xffffffffu, m, o));
  if ((threadIdx.x & 31) == 0) shm[threadIdx.x>>5] = m;
  __syncthreads();
  if (threadIdx.x == 0){
    float M = shm[0];
    #pragma unroll
    for (int i=1;i<8;i++) M = fmaxf(M, shm[i]);
    g_absmaxf[slot] = M;
  }
}

__device__ __forceinline__ int qv(float x, float qs){
  int v = (int)rintf(x * qs);        // RN = round half to even, matches jnp.round
  return (v == 128) ? -128 : v;      // int8 wrap of the +128 element
}

// quantize: warp per row, ds xnval identical to lnstats, ZERO FP64.
__device__ __forceinline__ void quant_warp(const float* src, int slot, int row){
  int lane = threadIdx.x & 31;
  float qs = 128.0f / g_absmaxf[slot];
  float4 lp = g_lnp[slot][row];        // (muh, mul, rh, rl)
  const float4* p = (const float4*)(src + (size_t)row*DM);
  u32* dst = g_xq[slot] + (size_t)row*KW;
  #pragma unroll
  for (int i=0;i<8;i++){
    float4 v = p[i*32 + lane];
    float a0 = xnval(v.x, lp.x, lp.y, lp.z, lp.w);
    float a1 = xnval(v.y, lp.x, lp.y, lp.z, lp.w);
    float a2 = xnval(v.z, lp.x, lp.y, lp.z, lp.w);
    float a3 = xnval(v.w, lp.x, lp.y, lp.z, lp.w);
    int a = qv(a0,qs), b = qv(a1,qs), c = qv(a2,qs), d = qv(a3,qs);
    dst[i*32 + lane] =
        (u32)(a & 0xff) | ((u32)(b & 0xff) << 8) |
        ((u32)(c & 0xff) << 16) | ((u32)(d & 0xff) << 24);
  }
}
__global__ void __launch_bounds__(256) k_quant3(const float* q, const float* k, const float* v){
  int slot = blockIdx.y;
  const float* src = (slot==0)?q : (slot==1)?k : v;
  quant_warp(src, slot, blockIdx.x*8 + (threadIdx.x >> 5));
}
__global__ void __launch_bounds__(256) k_quant1(){
  quant_warp(g_att, 3, blockIdx.x*8 + (threadIdx.x >> 5));
}

// ---------------- IMMA GEMM v2.1: ldmatrix + cp.async stage loads --------
__global__ void __launch_bounds__(256) k_gemm(float* Cext, int slot0){
  int slot = slot0 + blockIdx.z;
  const u32* X = g_xq[slot];
  const u32* W = g_wq[slot];
  float* C = (slot < 3) ? g_proj[slot] : Cext;
  int m0 = blockIdx.y * 128, n0 = blockIdx.x * 128;

  __shared__ u32 As[128*36];
  __shared__ u32 Bs[128*36];

  int tid = threadIdx.x;
  int lane = tid & 31, warp = tid >> 5;
  int wm = (warp >> 1) * 32, wn = (warp & 1) * 64;

  u32 as_base = (u32)__cvta_generic_to_shared(As);
  u32 bs_base = (u32)__cvta_generic_to_shared(Bs);

  u32 a_word = (u32)((wm + ((lane>>3)&1)*8 + (lane&7))*36 + (lane>>4)*4);
  u32 b_word = (u32)((wn + ((lane>>4)&1)*8 + (lane&7))*36 + ((lane>>3)&1)*4);

  int acc[2][8][4];
  #pragma unroll
  for (int mt=0;mt<2;mt++)
    #pragma unroll
    for (int nt=0;nt<8;nt++)
      #pragma unroll
      for (int i=0;i<4;i++) acc[mt][nt][i] = 0;

  for (int st = 0; st < 8; st++){            // 8 stages of K=128 bytes
    #pragma unroll
    for (int l=0;l<4;l++){
      int idx = tid + l*256;                 // 0..1023
      int row = idx >> 3, seg = (idx & 7) * 4;
      cpa16(as_base + (u32)(row*36 + seg)*4u, X + (size_t)(m0+row)*KW + st*32 + seg);
      cpa16(bs_base + (u32)(row*36 + seg)*4u, W + (size_t)(n0+row)*KW + st*32 + seg);
    }
    cpa_commit();
    asm volatile("cp.async.wait_group 0;");
    __syncthreads();
    #pragma unroll
    for (int s=0;s<4;s++){                   // four k32 steps per stage
      u32 afr[2][4], bfr[8][2];
      #pragma unroll
      for (int mt=0;mt<2;mt++){
        u32 addr = as_base + (a_word + (u32)(mt*16*36 + s*8))*4u;
        ldsm4(addr, afr[mt][0], afr[mt][1], afr[mt][2], afr[mt][3]);
      }
      #pragma unroll
      for (int np=0;np<4;np++){
        u32 addr = bs_base + (b_word + (u32)(np*16*36 + s*8))*4u;
        ldsm4(addr, bfr[2*np][0], bfr[2*np][1], bfr[2*np+1][0], bfr[2*np+1][1]);
      }
      #pragma unroll
      for (int mt=0;mt<2;mt++)
        #pragma unroll
        for (int nt=0;nt<8;nt++){
          asm volatile(
            "mma.sync.aligned.m16n8k32.row.col.s32.s8.s8.s32 "
            "{%0,%1,%2,%3}, {%4,%5,%6,%7}, {%8,%9}, {%0,%1,%2,%3};"
            : "+r"(acc[mt][nt][0]), "+r"(acc[mt][nt][1]),
              "+r"(acc[mt][nt][2]), "+r"(acc[mt][nt][3])
            : "r"(afr[mt][0]), "r"(afr[mt][1]), "r"(afr[mt][2]), "r"(afr[mt][3]),
              "r"(bfr[nt][0]), "r"(bfr[nt][1]));
        }
    }
    __syncthreads();
  }

  float scale = (g_absmaxf[slot] / 128.0f) * g_wbeta[slot];   // dequant * beta
  #pragma unroll
  for (int mt=0;mt<2;mt++){
    #pragma unroll
    for (int nt=0;nt<8;nt++){
      int r0 = m0 + wm + mt*16 + (lane >> 2);
      int c0 = n0 + wn + nt*8 + 2*(lane & 3);
      float2 v0, v1;
      v0.x = (float)acc[mt][nt][0] * scale;
      v0.y = (float)acc[mt][nt][1] * scale;
      v1.x = (float)acc[mt][nt][2] * scale;
      v1.y = (float)acc[mt][nt][3] * scale;
      *(float2*)(C + (size_t)r0*DM + c0)     = v0;
      *(float2*)(C + (size_t)(r0+8)*DM + c0) = v1;
    }
  }
}

__global__ void k_maskpack(const int* mask){
  int row = blockIdx.x;                 // b*2048 + q
  int lane = threadIdx.x & 31, wd = threadIdx.x >> 5;
  for (int w8 = 0; w8 < 8; w8++){
    int kk = w8*256 + threadIdx.x;
    int mv = mask[(size_t)row*2048 + kk];
    u32 bits = __ballot_sync(0xffffffffu, mv != 0);
    if (lane == 0) g_maskbits[(size_t)row*64 + w8*8 + wd] = bits;
  }
}

// Flash attention fp32/FFMA2. dk-split (2 threads/query) x 2 queries/thread
// (R9-proven, UNCHANGED). Smem rows: halves at word off 0/36, stride 72.
__global__ void __launch_bounds__(128,2) k_flash(){
  extern __shared__ float fsm[];        // K: [2][64][72]  V: [2][64][72]
  float* KS = fsm;
  float* VS = fsm + 2*64*TSTR;

  int tid = threadIdx.x;
  int p  = tid >> 1;                    // query pair index 0..63
  int hf = tid & 1;                     // dim half
  int qt = blockIdx.x & 15;
  int h  = (blockIdx.x >> 4) & 15;
  int b  = blockIdx.x >> 8;
  int qa = qt*128 + p;                  // query A; query B = qa + 64
  size_t qoffA = ((size_t)(b*2048 + qa))*DM + h*64 + hf*32;
  size_t qoffB = qoffA + (size_t)64*DM;
  const float* QP = g_proj[0];
  const float* KP = g_proj[1];
  const float* VP = g_proj[2];

  u32 ks_base = (u32)__cvta_generic_to_shared(KS);
  u32 vs_base = (u32)__cvta_generic_to_shared(VS);

  ull q2a[16], q2b[16];
  {
    const float4* pa = (const float4*)(QP + qoffA);
    const float4* pb = (const float4*)(QP + qoffB);
    #pragma unroll
    for (int t=0;t<8;t++){
      float4 fa = pa[t], fb = pb[t];
      q2a[2*t]   = pk2(fa.x*0.125f, fa.y*0.125f);  // fold 1/sqrt(64)
      q2a[2*t+1] = pk2(fa.z*0.125f, fa.w*0.125f);
      q2b[2*t]   = pk2(fb.x*0.125f, fb.y*0.125f);
      q2b[2*t+1] = pk2(fb.z*0.125f, fb.w*0.125f);
    }
  }
  ull acc2a[16], acc2b[16];
  #pragma unroll
  for (int t=0;t<16;t++){ acc2a[t] = 0ull; acc2b[t] = 0ull; }
  float ma = -1e30f, sa = 0.f, mb = -1e30f, sb = 0.f;

  const u32* mbaseA = g_maskbits + (size_t)(b*2048 + qa)*64;
  const u32* mbaseB = mbaseA + 64*64;

  #pragma unroll
  for (int l=0;l<8;l++){
    int i = tid + l*128;               // 0..1023
    int row = i >> 4, c = i & 15;
    int woff = row*TSTR + ((c < 8) ? c*4 : 36 + (c-8)*4);
    size_t goff = ((size_t)(b*2048 + row))*DM + h*64 + c*4;
    cpa16(ks_base + (u32)(woff*4), KP + goff);
    cpa16(vs_base + (u32)(woff*4), VP + goff);
  }
  cpa_commit();

  for (int kt = 0; kt < 32; kt++){
    int buf = kt & 1;
    if (kt < 31){
      int nb = buf ^ 1;
      #pragma unroll
      for (int l=0;l<8;l++){
        int i = tid + l*128;
        int row = i >> 4, c = i & 15;
        int woff = (nb*64 + row)*TSTR + ((c < 8) ? c*4 : 36 + (c-8)*4);
        size_t goff = ((size_t)(b*2048 + (kt+1)*64 + row))*DM + h*64 + c*4;
        cpa16(ks_base + (u32)(woff*4), KP + goff);
        cpa16(vs_base + (u32)(woff*4), VP + goff);
      }
      cpa_commit();
      asm volatile("cp.async.wait_group 1;");
    } else {
      asm volatile("cp.async.wait_group 0;");
    }
    __syncthreads();

    const float* kbuf = KS + buf*64*TSTR + hf*36;
    const float* vbuf = VS + buf*64*TSTR + hf*36;
    int k0 = kt*64;

    #pragma unroll 1
    for (int j0 = 0; j0 < 64; j0 += 8){
      u32 mbA = mbaseA[(k0 + j0) >> 5] >> (j0 & 31);
      u32 mbB = mbaseB[(k0 + j0) >> 5] >> (j0 & 31);
      float lgA[8], lgB[8];
      #pragma unroll
      for (int jj=0;jj<8;jj++){
        const ulonglong2* kp2 = (const ulonglong2*)(kbuf + (j0+jj)*TSTR);
        ull d0a = 0ull, d1a = 0ull, d0b = 0ull, d1b = 0ull;
        #pragma unroll
        for (int t=0;t<4;t++){
          ulonglong2 k1 = kp2[2*t];        // LDS.128, conflict-free pair
          ulonglong2 k2 = kp2[2*t+1];
          d0a = f2fma(q2a[4*t],   k1.x, d0a);
          d1a = f2fma(q2a[4*t+1], k1.y, d1a);
          d0a = f2fma(q2a[4*t+2], k2.x, d0a);
          d1a = f2fma(q2a[4*t+3], k2.y, d1a);
          d0b = f2fma(q2b[4*t],   k1.x, d0b);
          d1b = f2fma(q2b[4*t+1], k1.y, d1b);
          d0b = f2fma(q2b[4*t+2], k2.x, d0b);
          d1b = f2fma(q2b[4*t+3], k2.y, d1b);
        }
        float2 a0 = upk2(d0a), a1 = upk2(d1a);
        float2 b0 = upk2(d0b), b1 = upk2(d1b);
        float hA = (a0.x + a0.y) + (a1.x + a1.y);
        float hB = (b0.x + b0.y) + (b1.x + b1.y);
        float lvA = hA + __shfl_xor_sync(0xffffffffu, hA, 1);
        float lvB = hB + __shfl_xor_sync(0xffffffffu, hB, 1);
        lgA[jj] = ((mbA >> jj) & 1u) ? lvA : -1e9f;
        lgB[jj] = ((mbB >> jj) & 1u) ? lvB : -1e9f;
      }
      float cmA = lgA[0], cmB = lgB[0];
      #pragma unroll
      for (int jj=1;jj<8;jj++){
        cmA = fmaxf(cmA, lgA[jj]);
        cmB = fmaxf(cmB, lgB[jj]);
      }
      if (cmA > ma){
        float r = __expf(ma - cmA);
        sa *= r;
        ull rr = pk2(r, r);
        #pragma unroll
        for (int t=0;t<16;t++) acc2a[t] = f2mul(acc2a[t], rr);
        ma = cmA;
      }
      if (cmB > mb){
        float r = __expf(mb - cmB);
        sb *= r;
        ull rr = pk2(r, r);
        #pragma unroll
        for (int t=0;t<16;t++) acc2b[t] = f2mul(acc2b[t], rr);
        mb = cmB;
      }
      float pA[8], pB[8]; float psA = 0.f, psB = 0.f;
      #pragma unroll
      for (int jj=0;jj<8;jj++){
        pA[jj] = __expf(lgA[jj] - ma); psA += pA[jj];
        pB[jj] = __expf(lgB[jj] - mb); psB += pB[jj];
      }
      sa += psA; sb += psB;
      #pragma unroll
      for (int jj=0;jj<8;jj++){
        ull ppa = pk2(pA[jj], pA[jj]);
        ull ppb = pk2(pB[jj], pB[jj]);
        const ulonglong2* vp2 = (const ulonglong2*)(vbuf + (j0+jj)*TSTR);
        #pragma unroll
        for (int t=0;t<4;t++){
          ulonglong2 v1 = vp2[2*t];
          ulonglong2 v2 = vp2[2*t+1];
          acc2a[4*t]   = f2fma(ppa, v1.x, acc2a[4*t]);
          acc2a[4*t+1] = f2fma(ppa, v1.y, acc2a[4*t+1]);
          acc2a[4*t+2] = f2fma(ppa, v2.x, acc2a[4*t+2]);
          acc2a[4*t+3] = f2fma(ppa, v2.y, acc2a[4*t+3]);
          acc2b[4*t]   = f2fma(ppb, v1.x, acc2b[4*t]);
          acc2b[4*t+1] = f2fma(ppb, v1.y, acc2b[4*t+1]);
          acc2b[4*t+2] = f2fma(ppb, v2.x, acc2b[4*t+2]);
          acc2b[4*t+3] = f2fma(ppb, v2.y, acc2b[4*t+3]);
        }
      }
    }
    __syncthreads();
  }
  float invA = 1.0f / sa, invB = 1.0f / sb;
  float* orA = g_att + qoffA;
  float* orB = g_att + qoffB;
  #pragma unroll
  for (int t=0;t<16;t++){
    float2 fa = upk2(acc2a[t]);
    fa.x *= invA; fa.y *= invA;
    *(float2*)(orA + 2*t) = fa;
    float2 fb = upk2(acc2b[t]);
    fb.x *= invB; fb.y *= invB;
    *(float2*)(orB + 2*t) = fb;
  }
}

// ------------------------- launcher --------------------------------------
extern "C" void kernel_launch(void* const* d_in, const int* in_sizes, int n_in,
                              void* d_out, int out_size){
  const float* q   = (const float*)d_in[0];
  const float* k   = (const float*)d_in[1];
  const float* v   = (const float*)d_in[2];
  const int*  mask = (const int*)  d_in[3];
  const float* w0  = (const float*)d_in[4];  // wq_w
  const float* w1  = (const float*)d_in[5];  // wk_w
  const float* w2  = (const float*)d_in[6];  // wv_w
  const float* w3  = (const float*)d_in[7];  // w0_w
  float* out = (float*)d_out;

  const int FLASH_SMEM = 4*64*TSTR*4;   // 73728 bytes

  static int smem_set = 0;
  if (!smem_set){
    cudaFuncSetAttribute(k_flash, cudaFuncAttributeMaxDynamicSharedMemorySize, FLASH_SMEM);
    smem_set = 1;
  }

  k_wstats1<<<dim3(256,4),256>>>(w0,w1,w2,w3);   // (0)
  k_wstats2<<<4,256>>>();                        // (1)
  k_wquant<<<dim3(1024,4),256>>>(w0,w1,w2,w3);   // (2)

  k_lnstats3<<<dim3(512,3),256>>>(q,k,v);        // (3) <- profiled slot
  k_absmax<<<3,256>>>(0);                        // (4)
  k_quant3<<<dim3(512,3),256>>>(q,k,v);          // (5)

  k_gemm<<<dim3(8,32,3),256>>>(nullptr,0);       // (6) qp,kp,vp

  k_maskpack<<<4096,256>>>(mask);                // (7)
  k_flash<<<512,128,FLASH_SMEM>>>();             // (8)

  k_lnstats1<<<512,256>>>();                     // (9)
  k_absmax<<<1,256>>>(3);                        // (10)
  k_quant1<<<512,256>>>();                       // (11)
  k_gemm<<<dim3(8,32,1),256>>>(out,3);           // (12)
}

// round 15
// speedup vs baseline: 1.8766x; 1.1538x over previous
#include <cuda_runtime.h>
#include <cuda_bf16.h>
#include <math.h>

#define ROWS 4096          // B*S = 2*2048
#define DM   1024
#define KW   256           // 1024/4 packed words per row
#define NELEM (ROWS*DM)
#define TSTR 72            // padded smem row stride (words) for flash tiles

typedef unsigned int u32;
typedef unsigned long long ull;

// ------------------------- static device scratch (no allocs) -------------
__device__ u32    g_xq[4][ROWS*KW];     // int8-packed quantized activations
__device__ u32    g_wq[4][DM*KW];       // int8-packed sign weights
__device__ float  g_proj[3][NELEM];     // qp/kp/vp projections (fp32)
__device__ float  g_att[NELEM];         // attention output (concat heads)
__device__ float  g_wpart[4][256][4];   // weight-stat ff partials (s.h,s.l,a.h,a.l)
__device__ float  g_wbeta[4];           // written by wquant block 0
__device__ float4 g_lnp[4][ROWS];       // per-row LN params (muh, mul, rh, rl)
__device__ float  g_rowmax[4][ROWS];    // per-row absmax of normalized vals
__device__ float  g_absmaxf[4];         // written by quant block 0 (for gemm)
__device__ u32    g_maskbits[ROWS*64];  // bit-packed mask, 2048 bits/row

// ------------------------- float-float (ds) arithmetic -------------------
// FP64 on B300 is ~18.4 cyc/warp-instr/SM (crippled). All "double precision"
// work runs as fp32 pairs on the FMA pipe (R13/R14: bit-identical rel_err).
struct ff { float h, l; };

__device__ __forceinline__ ff two_sum(float a, float b){
  float s = a + b;
  float bb = s - a;
  float e = (a - (s - bb)) + (b - bb);
  ff r; r.h = s; r.l = e; return r;
}
__device__ __forceinline__ ff ff_norm(float h, float l){
  float s = h + l;
  ff r; r.h = s; r.l = l - (s - h); return r;
}
__device__ __forceinline__ ff ff_addf(ff a, float b){
  ff t = two_sum(a.h, b);
  return ff_norm(t.h, t.l + a.l);
}
__device__ __forceinline__ ff ff_addff(ff a, ff b){
  ff t = two_sum(a.h, b.h);
  return ff_norm(t.h, t.l + (a.l + b.l));
}
__device__ __forceinline__ ff ff_addsq(ff a, float x){  // a += x*x
  float p = x*x;
  float e = fmaf(x, x, -p);
  ff t = two_sum(a.h, p);
  return ff_norm(t.h, t.l + (a.l + e));
}
__device__ __forceinline__ ff ff_mul(ff a, ff b){
  float p = a.h * b.h;
  float e = fmaf(a.h, b.h, -p);
  e = fmaf(a.h, b.l, e);
  e = fmaf(a.l, b.h, e);
  return ff_norm(p, e);
}
// (x - mu) * r in ds, rounded once to fp32. Shared by lnstats and quant.
__device__ __forceinline__ float xnval(float x, float muh, float mul,
                                       float rh, float rl){
  ff d = two_sum(x, -muh);
  float dl = d.l - mul;
  float p = d.h * rh;
  float e = fmaf(d.h, rh, -p);
  e = fmaf(d.h, rl, e);
  e = fmaf(dl,  rh, e);
  return p + e;
}

// ------------------------- f32x2 packed helpers --------------------------
__device__ __forceinline__ ull pk2(float lo, float hi){
  ull r; asm("mov.b64 %0,{%1,%2};" : "=l"(r) : "f"(lo), "f"(hi)); return r;
}
__device__ __forceinline__ float2 upk2(ull v){
  float2 f; asm("mov.b64 {%0,%1},%2;" : "=f"(f.x), "=f"(f.y) : "l"(v)); return f;
}
__device__ __forceinline__ ull f2fma(ull a, ull b, ull c){
  ull r; asm("fma.rn.f32x2 %0,%1,%2,%3;" : "=l"(r) : "l"(a), "l"(b), "l"(c)); return r;
}
__device__ __forceinline__ ull f2mul(ull a, ull b){
  ull r; asm("mul.rn.f32x2 %0,%1,%2;" : "=l"(r) : "l"(a), "l"(b)); return r;
}

__device__ __forceinline__ void cpa16(u32 saddr, const void* g){
  asm volatile("cp.async.cg.shared.global [%0], [%1], 16;" :: "r"(saddr), "l"(g));
}
__device__ __forceinline__ void cpa_commit(){
  asm volatile("cp.async.commit_group;");
}

__device__ __forceinline__ void ldsm4(u32 addr, u32& r0, u32& r1, u32& r2, u32& r3){
  asm volatile("ldmatrix.sync.aligned.m8n8.x4.shared.b16 {%0,%1,%2,%3}, [%4];"
               : "=r"(r0), "=r"(r1), "=r"(r2), "=r"(r3) : "r"(addr));
}

// ------------------------- weight stats (ds) ------------------------------
__global__ void k_wstats1(const float* w0, const float* w1,
                          const float* w2, const float* w3){
  const float* w = (blockIdx.y==0)?w0 : (blockIdx.y==1)?w1 : (blockIdx.y==2)?w2 : w3;
  int base = blockIdx.x * 4096;
  ff s = {0.f,0.f}, a = {0.f,0.f};
  for (int i = threadIdx.x; i < 4096; i += 256){
    float v = w[base + i];
    s = ff_addf(s, v);
    a = ff_addf(a, fabsf(v));
  }
  #pragma unroll
  for (int o=16;o;o>>=1){
    ff t;
    t.h = __shfl_xor_sync(0xffffffffu, s.h, o);
    t.l = __shfl_xor_sync(0xffffffffu, s.l, o);
    s = ff_addff(s, t);
    t.h = __shfl_xor_sync(0xffffffffu, a.h, o);
    t.l = __shfl_xor_sync(0xffffffffu, a.l, o);
    a = ff_addff(a, t);
  }
  __shared__ float sh[8][4];
  if ((threadIdx.x & 31) == 0){
    int wi = threadIdx.x >> 5;
    sh[wi][0] = s.h; sh[wi][1] = s.l; sh[wi][2] = a.h; sh[wi][3] = a.l;
  }
  __syncthreads();
  if (threadIdx.x == 0){
    ff S = {sh[0][0], sh[0][1]}, A = {sh[0][2], sh[0][3]};
    #pragma unroll
    for (int i=1;i<8;i++){
      ff t1 = {sh[i][0], sh[i][1]}; S = ff_addff(S, t1);
      ff t2 = {sh[i][2], sh[i][3]}; A = ff_addff(A, t2);
    }
    g_wpart[blockIdx.y][blockIdx.x][0] = S.h;
    g_wpart[blockIdx.y][blockIdx.x][1] = S.l;
    g_wpart[blockIdx.y][blockIdx.x][2] = A.h;
    g_wpart[blockIdx.y][blockIdx.x][3] = A.l;
  }
}

// wquant with FUSED final stat reduction (identical tree to old wstats2 ->
// bit-identical mean/beta; every block recomputes, block 0 publishes beta).
__global__ void __launch_bounds__(256) k_wquant(const float* w0, const float* w1,
                         const float* w2, const float* w3){
  int wh = blockIdx.y;
  const float* w = (wh==0)?w0 : (wh==1)?w1 : (wh==2)?w2 : w3;

  __shared__ float sh[8][4];
  __shared__ float2 s_mean;
  ff s = {g_wpart[wh][threadIdx.x][0], g_wpart[wh][threadIdx.x][1]};
  ff a = {g_wpart[wh][threadIdx.x][2], g_wpart[wh][threadIdx.x][3]};
  #pragma unroll
  for (int o=16;o;o>>=1){
    ff t;
    t.h = __shfl_xor_sync(0xffffffffu, s.h, o);
    t.l = __shfl_xor_sync(0xffffffffu, s.l, o);
    s = ff_addff(s, t);
    t.h = __shfl_xor_sync(0xffffffffu, a.h, o);
    t.l = __shfl_xor_sync(0xffffffffu, a.l, o);
    a = ff_addff(a, t);
  }
  if ((threadIdx.x & 31) == 0){
    int wi = threadIdx.x >> 5;
    sh[wi][0] = s.h; sh[wi][1] = s.l; sh[wi][2] = a.h; sh[wi][3] = a.l;
  }
  __syncthreads();
  if (threadIdx.x == 0){
    ff S = {sh[0][0], sh[0][1]}, A = {sh[0][2], sh[0][3]};
    #pragma unroll
    for (int i=1;i<8;i++){
      ff t1 = {sh[i][0], sh[i][1]}; S = ff_addff(S, t1);
      ff t2 = {sh[i][2], sh[i][3]}; A = ff_addff(A, t2);
    }
    s_mean.x = S.h * (1.0f/1048576.0f);
    s_mean.y = S.l * (1.0f/1048576.0f);
    if (blockIdx.x == 0)
      g_wbeta[wh] = A.h * (1.0f/1048576.0f) + A.l * (1.0f/1048576.0f);
  }
  __syncthreads();
  float2 mu = s_mean;

  int o = blockIdx.x;
  float4 v = ((const float4*)(w + (size_t)o*DM))[threadIdx.x];
  int r[4];
  float xs[4] = {v.x, v.y, v.z, v.w};
  #pragma unroll
  for (int i=0;i<4;i++){
    ff d = two_sum(xs[i], -mu.x);
    float t = d.h + (d.l - mu.y);       // sign of (x - mean), ds accuracy
    r[i] = (t > 0.f) ? 1 : ((t < 0.f) ? -1 : 0);
  }
  g_wq[wh][(size_t)o*KW + threadIdx.x] =
      (u32)(r[0] & 0xff) | ((u32)(r[1] & 0xff) << 8) |
      ((u32)(r[2] & 0xff) << 16) | ((u32)(r[3] & 0xff) << 24);
}

// ---- LN stats: warp per row, ds arithmetic, ZERO FP64 -------------------
__device__ __forceinline__ void lnstats_warp(const float* src, int slot, int row){
  int lane = threadIdx.x & 31;
  const float4* p = (const float4*)(src + (size_t)row*DM);
  float4 vv[8];
  ff s = {0.f,0.f}, sq = {0.f,0.f};
  #pragma unroll
  for (int i=0;i<8;i++){
    float4 v = p[i*32 + lane];
    vv[i] = v;
    s = ff_addf(s, v.x);  s = ff_addf(s, v.y);
    s = ff_addf(s, v.z);  s = ff_addf(s, v.w);
    sq = ff_addsq(sq, v.x); sq = ff_addsq(sq, v.y);
    sq = ff_addsq(sq, v.z); sq = ff_addsq(sq, v.w);
  }
  #pragma unroll
  for (int o=16;o;o>>=1){
    ff t;
    t.h = __shfl_xor_sync(0xffffffffu, s.h, o);
    t.l = __shfl_xor_sync(0xffffffffu, s.l, o);
    s = ff_addff(s, t);
    t.h = __shfl_xor_sync(0xffffffffu, sq.h, o);
    t.l = __shfl_xor_sync(0xffffffffu, sq.l, o);
    sq = ff_addff(sq, t);
  }
  ff mu;  mu.h = s.h  * (1.0f/1024.0f); mu.l = s.l  * (1.0f/1024.0f);
  ff qm;  qm.h = sq.h * (1.0f/1024.0f); qm.l = sq.l * (1.0f/1024.0f);
  ff m2 = ff_mul(mu, mu);
  ff nm2; nm2.h = -m2.h; nm2.l = -m2.l;
  ff var = ff_addff(qm, nm2);
  var = ff_addf(var, 1e-5f);
  float y0 = rsqrtf(var.h);
  y0 = y0 * (1.5f - 0.5f * var.h * y0 * y0);
  ff y = {y0, 0.f};
  #pragma unroll
  for (int it=0; it<2; it++){
    ff t = ff_mul(y, y);
    t = ff_mul(var, t);
    ff u; u.h = -0.5f*t.h; u.l = -0.5f*t.l;
    u = ff_addf(u, 1.5f);
    y = ff_mul(y, u);
  }
  float am = 0.f;
  #pragma unroll
  for (int i=0;i<8;i++){
    float a0 = xnval(vv[i].x, mu.h, mu.l, y.h, y.l);
    float a1 = xnval(vv[i].y, mu.h, mu.l, y.h, y.l);
    float a2 = xnval(vv[i].z, mu.h, mu.l, y.h, y.l);
    float a3 = xnval(vv[i].w, mu.h, mu.l, y.h, y.l);
    am = fmaxf(am, fmaxf(fmaxf(fabsf(a0), fabsf(a1)), fmaxf(fabsf(a2), fabsf(a3))));
  }
  #pragma unroll
  for (int o=16;o;o>>=1) am = fmaxf(am, __shfl_xor_sync(0xffffffffu, am, o));
  if (lane == 0){
    g_lnp[slot][row] = make_float4(mu.h, mu.l, y.h, y.l);
    g_rowmax[slot][row] = am;
  }
}

__global__ void __launch_bounds__(256) k_lnstats3(const float* q, const float* k, const float* v){
  int slot = blockIdx.y;
  const float* src = (slot==0)?q : (slot==1)?k : v;
  lnstats_warp(src, slot, blockIdx.x*8 + (threadIdx.x >> 5));
}
__global__ void __launch_bounds__(256) k_lnstats1(){
  lnstats_warp(g_att, 3, blockIdx.x*8 + (threadIdx.x >> 5));
}

__device__ __forceinline__ int qv(float x, float qs){
  int v = (int)rintf(x * qs);        // RN = round half to even, matches jnp.round
  return (v == 128) ? -128 : v;      // int8 wrap of the +128 element
}

// In-block global absmax (identical tree to old k_absmax -> bit-identical).
__device__ __forceinline__ float block_absmax(int slot){
  __shared__ float shm[8];
  __shared__ float s_mx;
  float m = 0.f;
  for (int i = threadIdx.x; i < ROWS; i += 256)
    m = fmaxf(m, g_rowmax[slot][i]);
  #pragma unroll
  for (int o=16;o;o>>=1) m = fmaxf(m, __shfl_xor_sync(0xffffffffu, m, o));
  if ((threadIdx.x & 31) == 0) shm[threadIdx.x>>5] = m;
  __syncthreads();
  if (threadIdx.x == 0){
    float M = shm[0];
    #pragma unroll
    for (int i=1;i<8;i++) M = fmaxf(M, shm[i]);
    s_mx = M;
  }
  __syncthreads();
  return s_mx;
}

// quantize: warp per row, 8 rows/CTA, fused absmax; block 0 publishes it.
__device__ __forceinline__ void quant_warp(const float* src, int slot, int row, float qs){
  int lane = threadIdx.x & 31;
  float4 lp = g_lnp[slot][row];        // (muh, mul, rh, rl)
  const float4* p = (const float4*)(src + (size_t)row*DM);
  u32* dst = g_xq[slot] + (size_t)row*KW;
  #pragma unroll
  for (int i=0;i<8;i++){
    float4 v = p[i*32 + lane];
    float a0 = xnval(v.x, lp.x, lp.y, lp.z, lp.w);
    float a1 = xnval(v.y, lp.x, lp.y, lp.z, lp.w);
    float a2 = xnval(v.z, lp.x, lp.y, lp.z, lp.w);
    float a3 = xnval(v.w, lp.x, lp.y, lp.z, lp.w);
    int a = qv(a0,qs), b = qv(a1,qs), c = qv(a2,qs), d = qv(a3,qs);
    dst[i*32 + lane] =
        (u32)(a & 0xff) | ((u32)(b & 0xff) << 8) |
        ((u32)(c & 0xff) << 16) | ((u32)(d & 0xff) << 24);
  }
}
__global__ void __launch_bounds__(256) k_quant3(const float* q, const float* k, const float* v){
  int slot = blockIdx.y;
  const float* src = (slot==0)?q : (slot==1)?k : v;
  float mx = block_absmax(slot);
  if (blockIdx.x == 0 && threadIdx.x == 0) g_absmaxf[slot] = mx;
  quant_warp(src, slot, blockIdx.x*8 + (threadIdx.x >> 5), 128.0f/mx);
}
__global__ void __launch_bounds__(256) k_quant1(){
  float mx = block_absmax(3);
  if (blockIdx.x == 0 && threadIdx.x == 0) g_absmaxf[3] = mx;
  quant_warp(g_att, 3, blockIdx.x*8 + (threadIdx.x >> 5), 128.0f/mx);
}

// ---------------- IMMA GEMM v2.1: ldmatrix + cp.async stage loads --------
__global__ void __launch_bounds__(256) k_gemm(float* Cext, int slot0){
  int slot = slot0 + blockIdx.z;
  const u32* X = g_xq[slot];
  const u32* W = g_wq[slot];
  float* C = (slot < 3) ? g_proj[slot] : Cext;
  int m0 = blockIdx.y * 128, n0 = blockIdx.x * 128;

  __shared__ u32 As[128*36];
  __shared__ u32 Bs[128*36];

  int tid = threadIdx.x;
  int lane = tid & 31, warp = tid >> 5;
  int wm = (warp >> 1) * 32, wn = (warp & 1) * 64;

  u32 as_base = (u32)__cvta_generic_to_shared(As);
  u32 bs_base = (u32)__cvta_generic_to_shared(Bs);

  u32 a_word = (u32)((wm + ((lane>>3)&1)*8 + (lane&7))*36 + (lane>>4)*4);
  u32 b_word = (u32)((wn + ((lane>>4)&1)*8 + (lane&7))*36 + ((lane>>3)&1)*4);

  int acc[2][8][4];
  #pragma unroll
  for (int mt=0;mt<2;mt++)
    #pragma unroll
    for (int nt=0;nt<8;nt++)
      #pragma unroll
      for (int i=0;i<4;i++) acc[mt][nt][i] = 0;

  for (int st = 0; st < 8; st++){            // 8 stages of K=128 bytes
    #pragma unroll
    for (int l=0;l<4;l++){
      int idx = tid + l*256;                 // 0..1023
      int row = idx >> 3, seg = (idx & 7) * 4;
      cpa16(as_base + (u32)(row*36 + seg)*4u, X + (size_t)(m0+row)*KW + st*32 + seg);
      cpa16(bs_base + (u32)(row*36 + seg)*4u, W + (size_t)(n0+row)*KW + st*32 + seg);
    }
    cpa_commit();
    asm volatile("cp.async.wait_group 0;");
    __syncthreads();
    #pragma unroll
    for (int s=0;s<4;s++){                   // four k32 steps per stage
      u32 afr[2][4], bfr[8][2];
      #pragma unroll
      for (int mt=0;mt<2;mt++){
        u32 addr = as_base + (a_word + (u32)(mt*16*36 + s*8))*4u;
        ldsm4(addr, afr[mt][0], afr[mt][1], afr[mt][2], afr[mt][3]);
      }
      #pragma unroll
      for (int np=0;np<4;np++){
        u32 addr = bs_base + (b_word + (u32)(np*16*36 + s*8))*4u;
        ldsm4(addr, bfr[2*np][0], bfr[2*np][1], bfr[2*np+1][0], bfr[2*np+1][1]);
      }
      #pragma unroll
      for (int mt=0;mt<2;mt++)
        #pragma unroll
        for (int nt=0;nt<8;nt++){
          asm volatile(
            "mma.sync.aligned.m16n8k32.row.col.s32.s8.s8.s32 "
            "{%0,%1,%2,%3}, {%4,%5,%6,%7}, {%8,%9}, {%0,%1,%2,%3};"
            : "+r"(acc[mt][nt][0]), "+r"(acc[mt][nt][1]),
              "+r"(acc[mt][nt][2]), "+r"(acc[mt][nt][3])
            : "r"(afr[mt][0]), "r"(afr[mt][1]), "r"(afr[mt][2]), "r"(afr[mt][3]),
              "r"(bfr[nt][0]), "r"(bfr[nt][1]));
        }
    }
    __syncthreads();
  }

  float scale = (g_absmaxf[slot] / 128.0f) * g_wbeta[slot];   // dequant * beta
  #pragma unroll
  for (int mt=0;mt<2;mt++){
    #pragma unroll
    for (int nt=0;nt<8;nt++){
      int r0 = m0 + wm + mt*16 + (lane >> 2);
      int c0 = n0 + wn + nt*8 + 2*(lane & 3);
      float2 v0, v1;
      v0.x = (float)acc[mt][nt][0] * scale;
      v0.y = (float)acc[mt][nt][1] * scale;
      v1.x = (float)acc[mt][nt][2] * scale;
      v1.y = (float)acc[mt][nt][3] * scale;
      *(float2*)(C + (size_t)r0*DM + c0)     = v0;
      *(float2*)(C + (size_t)(r0+8)*DM + c0) = v1;
    }
  }
}

__global__ void k_maskpack(const int* mask){
  int row = blockIdx.x;                 // b*2048 + q
  int lane = threadIdx.x & 31, wd = threadIdx.x >> 5;
  for (int w8 = 0; w8 < 8; w8++){
    int kk = w8*256 + threadIdx.x;
    int mv = mask[(size_t)row*2048 + kk];
    u32 bits = __ballot_sync(0xffffffffu, mv != 0);
    if (lane == 0) g_maskbits[(size_t)row*64 + w8*8 + wd] = bits;
  }
}

// Flash attention fp32/FFMA2. dk-split x 2 queries/thread (R9-proven).
// NEW: exact-zero group skip — if every logit in the 8-key group is >=105
// below the running max, exp() underflows to exactly 0 (even as denormal,
// 2^-151 < 2^-149), so rescale+exp+PV contribute exactly nothing and are
// skipped bit-exactly. Near-one-hot softmax makes this the common case.
__global__ void __launch_bounds__(128,2) k_flash(){
  extern __shared__ float fsm[];        // K: [2][64][72]  V: [2][64][72]
  float* KS = fsm;
  float* VS = fsm + 2*64*TSTR;

  int tid = threadIdx.x;
  int p  = tid >> 1;                    // query pair index 0..63
  int hf = tid & 1;                     // dim half
  int qt = blockIdx.x & 15;
  int h  = (blockIdx.x >> 4) & 15;
  int b  = blockIdx.x >> 8;
  int qa = qt*128 + p;                  // query A; query B = qa + 64
  size_t qoffA = ((size_t)(b*2048 + qa))*DM + h*64 + hf*32;
  size_t qoffB = qoffA + (size_t)64*DM;
  const float* QP = g_proj[0];
  const float* KP = g_proj[1];
  const float* VP = g_proj[2];

  u32 ks_base = (u32)__cvta_generic_to_shared(KS);
  u32 vs_base = (u32)__cvta_generic_to_shared(VS);

  ull q2a[16], q2b[16];
  {
    const float4* pa = (const float4*)(QP + qoffA);
    const float4* pb = (const float4*)(QP + qoffB);
    #pragma unroll
    for (int t=0;t<8;t++){
      float4 fa = pa[t], fb = pb[t];
      q2a[2*t]   = pk2(fa.x*0.125f, fa.y*0.125f);  // fold 1/sqrt(64)
      q2a[2*t+1] = pk2(fa.z*0.125f, fa.w*0.125f);
      q2b[2*t]   = pk2(fb.x*0.125f, fb.y*0.125f);
      q2b[2*t+1] = pk2(fb.z*0.125f, fb.w*0.125f);
    }
  }
  ull acc2a[16], acc2b[16];
  #pragma unroll
  for (int t=0;t<16;t++){ acc2a[t] = 0ull; acc2b[t] = 0ull; }
  float ma = -1e30f, sa = 0.f, mb = -1e30f, sb = 0.f;

  const u32* mbaseA = g_maskbits + (size_t)(b*2048 + qa)*64;
  const u32* mbaseB = mbaseA + 64*64;

  #pragma unroll
  for (int l=0;l<8;l++){
    int i = tid + l*128;               // 0..1023
    int row = i >> 4, c = i & 15;
    int woff = row*TSTR + ((c < 8) ? c*4 : 36 + (c-8)*4);
    size_t goff = ((size_t)(b*2048 + row))*DM + h*64 + c*4;
    cpa16(ks_base + (u32)(woff*4), KP + goff);
    cpa16(vs_base + (u32)(woff*4), VP + goff);
  }
  cpa_commit();

  for (int kt = 0; kt < 32; kt++){
    int buf = kt & 1;
    if (kt < 31){
      int nb = buf ^ 1;
      #pragma unroll
      for (int l=0;l<8;l++){
        int i = tid + l*128;
        int row = i >> 4, c = i & 15;
        int woff = (nb*64 + row)*TSTR + ((c < 8) ? c*4 : 36 + (c-8)*4);
        size_t goff = ((size_t)(b*2048 + (kt+1)*64 + row))*DM + h*64 + c*4;
        cpa16(ks_base + (u32)(woff*4), KP + goff);
        cpa16(vs_base + (u32)(woff*4), VP + goff);
      }
      cpa_commit();
      asm volatile("cp.async.wait_group 1;");
    } else {
      asm volatile("cp.async.wait_group 0;");
    }
    __syncthreads();

    const float* kbuf = KS + buf*64*TSTR + hf*36;
    const float* vbuf = VS + buf*64*TSTR + hf*36;
    int k0 = kt*64;

    #pragma unroll 1
    for (int j0 = 0; j0 < 64; j0 += 8){
      u32 mbA = mbaseA[(k0 + j0) >> 5] >> (j0 & 31);
      u32 mbB = mbaseB[(k0 + j0) >> 5] >> (j0 & 31);
      float lgA[8], lgB[8];
      #pragma unroll
      for (int jj=0;jj<8;jj++){
        const ulonglong2* kp2 = (const ulonglong2*)(kbuf + (j0+jj)*TSTR);
        ull d0a = 0ull, d1a = 0ull, d0b = 0ull, d1b = 0ull;
        #pragma unroll
        for (int t=0;t<4;t++){
          ulonglong2 k1 = kp2[2*t];        // LDS.128, conflict-free pair
          ulonglong2 k2 = kp2[2*t+1];
          d0a = f2fma(q2a[4*t],   k1.x, d0a);
          d1a = f2fma(q2a[4*t+1], k1.y, d1a);
          d0a = f2fma(q2a[4*t+2], k2.x, d0a);
          d1a = f2fma(q2a[4*t+3], k2.y, d1a);
          d0b = f2fma(q2b[4*t],   k1.x, d0b);
          d1b = f2fma(q2b[4*t+1], k1.y, d1b);
          d0b = f2fma(q2b[4*t+2], k2.x, d0b);
          d1b = f2fma(q2b[4*t+3], k2.y, d1b);
        }
        float2 a0 = upk2(d0a), a1 = upk2(d1a);
        float2 b0 = upk2(d0b), b1 = upk2(d1b);
        float hA = (a0.x + a0.y) + (a1.x + a1.y);
        float hB = (b0.x + b0.y) + (b1.x + b1.y);
        float lvA = hA + __shfl_xor_sync(0xffffffffu, hA, 1);
        float lvB = hB + __shfl_xor_sync(0xffffffffu, hB, 1);
        lgA[jj] = ((mbA >> jj) & 1u) ? lvA : -1e9f;
        lgB[jj] = ((mbB >> jj) & 1u) ? lvB : -1e9f;
      }
      float cmA = lgA[0], cmB = lgB[0];
      #pragma unroll
      for (int jj=1;jj<8;jj++){
        cmA = fmaxf(cmA, lgA[jj]);
        cmB = fmaxf(cmB, lgB[jj]);
      }
      // exact-zero skip: below threshold exp() == 0 exactly for all 16 logits
      if (fmaxf(cmA - ma, cmB - mb) > -105.f){
        if (cmA > ma){
          float r = __expf(ma - cmA);
          sa *= r;
          ull rr = pk2(r, r);
          #pragma unroll
          for (int t=0;t<16;t++) acc2a[t] = f2mul(acc2a[t], rr);
          ma = cmA;
        }
        if (cmB > mb){
          float r = __expf(mb - cmB);
          sb *= r;
          ull rr = pk2(r, r);
          #pragma unroll
          for (int t=0;t<16;t++) acc2b[t] = f2mul(acc2b[t], rr);
          mb = cmB;
        }
        float pA[8], pB[8]; float psA = 0.f, psB = 0.f;
        #pragma unroll
        for (int jj=0;jj<8;jj++){
          pA[jj] = __expf(lgA[jj] - ma); psA += pA[jj];
          pB[jj] = __expf(lgB[jj] - mb); psB += pB[jj];
        }
        sa += psA; sb += psB;
        #pragma unroll
        for (int jj=0;jj<8;jj++){
          ull ppa = pk2(pA[jj], pA[jj]);
          ull ppb = pk2(pB[jj], pB[jj]);
          const ulonglong2* vp2 = (const ulonglong2*)(vbuf + (j0+jj)*TSTR);
          #pragma unroll
          for (int t=0;t<4;t++){
            ulonglong2 v1 = vp2[2*t];
            ulonglong2 v2 = vp2[2*t+1];
            acc2a[4*t]   = f2fma(ppa, v1.x, acc2a[4*t]);
            acc2a[4*t+1] = f2fma(ppa, v1.y, acc2a[4*t+1]);
            acc2a[4*t+2] = f2fma(ppa, v2.x, acc2a[4*t+2]);
            acc2a[4*t+3] = f2fma(ppa, v2.y, acc2a[4*t+3]);
            acc2b[4*t]   = f2fma(ppb, v1.x, acc2b[4*t]);
            acc2b[4*t+1] = f2fma(ppb, v1.y, acc2b[4*t+1]);
            acc2b[4*t+2] = f2fma(ppb, v2.x, acc2b[4*t+2]);
            acc2b[4*t+3] = f2fma(ppb, v2.y, acc2b[4*t+3]);
          }
        }
      }
    }
    __syncthreads();
  }
  float invA = 1.0f / sa, invB = 1.0f / sb;
  float* orA = g_att + qoffA;
  float* orB = g_att + qoffB;
  #pragma unroll
  for (int t=0;t<16;t++){
    float2 fa = upk2(acc2a[t]);
    fa.x *= invA; fa.y *= invA;
    *(float2*)(orA + 2*t) = fa;
    float2 fb = upk2(acc2b[t]);
    fb.x *= invB; fb.y *= invB;
    *(float2*)(orB + 2*t) = fb;
  }
}

// ------------------------- launcher --------------------------------------
extern "C" void kernel_launch(void* const* d_in, const int* in_sizes, int n_in,
                              void* d_out, int out_size){
  const float* q   = (const float*)d_in[0];
  const float* k   = (const float*)d_in[1];
  const float* v   = (const float*)d_in[2];
  const int*  mask = (const int*)  d_in[3];
  const float* w0  = (const float*)d_in[4];  // wq_w
  const float* w1  = (const float*)d_in[5];  // wk_w
  const float* w2  = (const float*)d_in[6];  // wv_w
  const float* w3  = (const float*)d_in[7];  // w0_w
  float* out = (float*)d_out;

  const int FLASH_SMEM = 4*64*TSTR*4;   // 73728 bytes

  static int smem_set = 0;
  if (!smem_set){
    cudaFuncSetAttribute(k_flash, cudaFuncAttributeMaxDynamicSharedMemorySize, FLASH_SMEM);
    smem_set = 1;
  }

  k_wstats1<<<dim3(256,4),256>>>(w0,w1,w2,w3);   // (0)
  k_wquant<<<dim3(1024,4),256>>>(w0,w1,w2,w3);   // (1) fused stat-final
  k_lnstats3<<<dim3(512,3),256>>>(q,k,v);        // (2)
  k_quant3<<<dim3(512,3),256>>>(q,k,v);          // (3) <- profiled (fused absmax)

  k_gemm<<<dim3(8,32,3),256>>>(nullptr,0);       // (4) qp,kp,vp
  k_maskpack<<<4096,256>>>(mask);                // (5)
  k_flash<<<512,128,FLASH_SMEM>>>();             // (6)

  k_lnstats1<<<512,256>>>();                     // (7)
  k_quant1<<<512,256>>>();                       // (8)
  k_gemm<<<dim3(8,32,1),256>>>(out,3);           // (9)
}